// round 3
// baseline (speedup 1.0000x reference)
#include <cuda_runtime.h>
#include <cuda_bf16.h>

#define BB 32
#define SS 400
#define LL 50
#define EE 256
#define HH 512
#define AD 64
#define VV 50000
#define G3 (3*HH)
#define DKX (EE+HH+2*AD)

__device__ float g_x[SS*BB*EE];
__device__ float g_gi_f[SS*BB*G3];
__device__ float g_gi_b[SS*BB*G3];
__device__ float g_hs_f[SS*BB*HH];
__device__ float g_hs_b[SS*BB*HH];
__device__ float g_h[2][2][BB*HH];
__device__ float g_EH[(long)BB*SS*2*HH];
__device__ float g_PK[(long)BB*SS*HH];
__device__ float g_encfin[BB*2*HH];
__device__ float g_pe[LL*BB*EE];
__device__ float g_up[BB*2*AD];
__device__ float g_dech[2][BB*HH];
__device__ float g_chvec[BB*HH];
__device__ float g_qW[BB*HH];
__device__ float g_scores[BB*SS];
__device__ float g_alphas[BB*SS];
__device__ float g_context[BB*2*HH];
__device__ float g_logits[BB*VV];
__device__ float g_gp[BB];
__device__ float g_vmax[BB];
__device__ float g_vinv[BB];

__device__ __forceinline__ float warp_sum(float v){
  #pragma unroll
  for (int o=16;o;o>>=1) v += __shfl_xor_sync(0xffffffffu,v,o);
  return v;
}
__device__ __forceinline__ float sigf(float x){ return __fdividef(1.f,1.f+__expf(-x)); }
__device__ __forceinline__ float tanh_acc(float x){
  float ax=fabsf(x), e=__expf(-2.f*ax);
  float r=__fdividef(1.f-e,1.f+e);
  return (x<0.f)?-r:r;
}

__global__ void k_embed(const int* __restrict__ src,const int* __restrict__ trg,
                        const int* __restrict__ user,const int* __restrict__ prod,
                        const float* __restrict__ embW,const float* __restrict__ userW,
                        const float* __restrict__ prodW){
  int t0=blockIdx.x*blockDim.x+threadIdx.x, st=gridDim.x*blockDim.x;
  for (int i=t0;i<SS*BB*EE;i+=st){
    int e=i%EE, sb=i/EE, b=sb%BB, s=sb/BB;
    g_x[i]=embW[(long)src[b*SS+s]*EE+e];
  }
  for (int i=t0;i<LL*BB*EE;i+=st){
    int e=i%EE, tb=i/EE, b=tb%BB, t=tb/BB;
    int tok=(t==0)?1:trg[b*LL+t-1];
    g_pe[i]=embW[(long)tok*EE+e];
  }
  for (int i=t0;i<BB*2*AD;i+=st){
    int k=i%(2*AD), b=i/(2*AD);
    g_up[i]=(k<AD)?userW[(long)user[b]*AD+k]:prodW[(long)prod[b]*AD+(k-AD)];
  }
  for (int i=t0;i<2*BB*HH;i+=st){
    int d=i/(BB*HH);
    g_h[d][0][i-d*BB*HH]=0.f;
  }
}

template<int BM,int BN,int BK,int TM,int TN>
__global__ void gemm_atb(const float* __restrict__ A,const float* __restrict__ W,
                         const float* __restrict__ bias,float* __restrict__ C,
                         int M,int N,int K){
  constexpr int THREADS=(BM/TM)*(BN/TN);
  __shared__ float As[BK][BM+1];
  __shared__ float Ws[BK][BN+1];
  int m0=blockIdx.y*BM, n0=blockIdx.x*BN, tid=threadIdx.x;
  int tn=tid%(BN/TN), tm=tid/(BN/TN);
  float acc[TM][TN];
  #pragma unroll
  for (int i=0;i<TM;i++)
    #pragma unroll
    for (int j=0;j<TN;j++) acc[i][j]=0.f;
  for (int k0=0;k0<K;k0+=BK){
    for (int i=tid;i<BM*BK;i+=THREADS){
      int r=i/BK,c=i%BK; int m=m0+r;
      As[c][r]=(m<M)?A[(long)m*K+k0+c]:0.f;
    }
    for (int i=tid;i<BN*BK;i+=THREADS){
      int r=i/BK,c=i%BK; int n=n0+r;
      Ws[c][r]=(n<N)?W[(long)n*K+k0+c]:0.f;
    }
    __syncthreads();
    #pragma unroll
    for (int k=0;k<BK;k++){
      float a[TM],w[TN];
      #pragma unroll
      for (int i=0;i<TM;i++) a[i]=As[k][tm*TM+i];
      #pragma unroll
      for (int j=0;j<TN;j++) w[j]=Ws[k][tn*TN+j];
      #pragma unroll
      for (int i=0;i<TM;i++)
        #pragma unroll
        for (int j=0;j<TN;j++) acc[i][j]+=a[i]*w[j];
    }
    __syncthreads();
  }
  #pragma unroll
  for (int i=0;i<TM;i++){
    int m=m0+tm*TM+i; if(m>=M) continue;
    #pragma unroll
    for (int j=0;j<TN;j++){
      int n=n0+tn*TN+j; if(n>=N) continue;
      C[(long)m*N+n]=acc[i][j]+(bias?bias[n]:0.f);
    }
  }
}

#define SMEM_ENC (BB*(HH+1)*4)
__global__ void k_enc_step(int s,int par,
                           const float* __restrict__ WhhF,const float* __restrict__ bhhF,
                           const float* __restrict__ WhhB,const float* __restrict__ bhhB){
  extern __shared__ float hs[];
  int dir=blockIdx.x>>6, chunk=blockIdx.x&63;
  const float* Whh=dir?WhhB:WhhF;
  const float* bhh=dir?bhhB:bhhF;
  const float* gi =dir?g_gi_b:g_gi_f;
  int sx=dir?(SS-1-s):s;
  const float* hprev=g_h[dir][par];
  float* hnext=g_h[dir][par^1];
  float* hout =dir?g_hs_b:g_hs_f;
  int tid=threadIdx.x;
  for (int i=tid;i<BB*HH;i+=128){ int b=i>>9,k=i&511; hs[b*(HH+1)+k]=hprev[i]; }
  __syncthreads();
  int b=tid&31, jl=tid>>5;
  int j0=chunk*8+jl*2;
  const float* hb=hs+b*(HH+1);
  const float* w0r=Whh+(j0+0)*HH;    const float* w1r=Whh+(j0+1)*HH;
  const float* w0z=Whh+(HH+j0+0)*HH; const float* w1z=Whh+(HH+j0+1)*HH;
  const float* w0n=Whh+(2*HH+j0)*HH; const float* w1n=Whh+(2*HH+j0+1)*HH;
  float a0r=0,a0z=0,a0n=0,a1r=0,a1z=0,a1n=0;
  #pragma unroll 2
  for (int k=0;k<HH;k+=4){
    float h0=hb[k],h1=hb[k+1],h2=hb[k+2],h3=hb[k+3];
    float4 w;
    w=*(const float4*)(w0r+k); a0r+=w.x*h0+w.y*h1+w.z*h2+w.w*h3;
    w=*(const float4*)(w1r+k); a1r+=w.x*h0+w.y*h1+w.z*h2+w.w*h3;
    w=*(const float4*)(w0z+k); a0z+=w.x*h0+w.y*h1+w.z*h2+w.w*h3;
    w=*(const float4*)(w1z+k); a1z+=w.x*h0+w.y*h1+w.z*h2+w.w*h3;
    w=*(const float4*)(w0n+k); a0n+=w.x*h0+w.y*h1+w.z*h2+w.w*h3;
    w=*(const float4*)(w1n+k); a1n+=w.x*h0+w.y*h1+w.z*h2+w.w*h3;
  }
  long gio=((long)sx*BB+b)*G3;
  float ar[2]={a0r,a1r}, az[2]={a0z,a1z}, an[2]={a0n,a1n};
  #pragma unroll
  for (int jj=0;jj<2;jj++){
    int j=j0+jj;
    float ir=gi[gio+j], iz=gi[gio+HH+j], in_=gi[gio+2*HH+j];
    float hr=ar[jj]+bhh[j], hz=az[jj]+bhh[HH+j], hn=an[jj]+bhh[2*HH+j];
    float r=sigf(ir+hr), z=sigf(iz+hz);
    float n=tanh_acc(in_+r*hn);
    float hv=(1.f-z)*n+z*hb[j];
    hnext[b*HH+j]=hv;
    hout[((long)sx*BB+b)*HH+j]=hv;
  }
}

__global__ void k_postenc(){
  int t0=blockIdx.x*blockDim.x+threadIdx.x, st=gridDim.x*blockDim.x;
  for (int i=t0;i<BB*2*HH;i+=st){
    int b=i/(2*HH), k=i%(2*HH);
    g_encfin[i]=(k<HH)?g_hs_f[((long)399*BB+b)*HH+k]:g_hs_b[((long)0*BB+b)*HH+(k-HH)];
  }
  for (long i=t0;i<(long)BB*SS*2*HH;i+=st){
    int d=(int)(i%(2*HH));
    long bs=i/(2*HH);
    int s=(int)(bs%SS), b=(int)(bs/SS);
    g_EH[i]=(d<HH)?g_hs_f[((long)s*BB+b)*HH+d]:g_hs_b[((long)s*BB+b)*HH+(d-HH)];
  }
}

__global__ void k_hidden(const float* __restrict__ initW,const float* __restrict__ initB){
  int b=blockIdx.y;
  int n=blockIdx.x*8+(threadIdx.x>>5);
  int lane=threadIdx.x&31;
  const float* f=g_encfin+b*2*HH;
  const float* w=initW+n*2*HH;
  float acc=0;
  for (int k=lane;k<2*HH;k+=32) acc+=f[k]*w[k];
  acc=warp_sum(acc);
  if (lane==0){
    float hv=tanh_acc(acc+initB[n]);
    g_dech[0][b*HH+n]=hv;
    g_chvec[b*HH+n]=hv;
  }
}

#define SMEM_DEC ((BB*(HH+1)+BB*(DKX+1))*4)
__global__ void k_dec_step(int t,int par,
                           const float* __restrict__ Wih,const float* __restrict__ Whh,
                           const float* __restrict__ bih,const float* __restrict__ bhh){
  extern __shared__ float sm[];
  float* hs=sm;
  float* xs=sm+BB*(HH+1);
  int tid=threadIdx.x;
  const float* hprev=g_dech[par];
  float* hnext=g_dech[par^1];
  for (int i=tid;i<BB*HH;i+=128){ int b=i>>9,k=i&511; hs[b*(HH+1)+k]=hprev[i]; }
  for (int i=tid;i<BB*DKX;i+=128){
    int b=i/DKX, k=i%DKX; float v;
    if (k<EE) v=g_pe[(t*BB+b)*EE+k];
    else if (k<EE+HH) v=g_chvec[b*HH+(k-EE)];
    else v=g_up[b*2*AD+(k-EE-HH)];
    xs[b*(DKX+1)+k]=v;
  }
  __syncthreads();
  int b=tid&31, jl=tid>>5;
  int j0=blockIdx.x*8+jl*2;
  const float* hb=hs+b*(HH+1);
  const float* xb=xs+b*(DKX+1);
  float xr[2]={0,0},xz[2]={0,0},xn[2]={0,0};
  {
    const float* w0r=Wih+(long)(j0+0)*DKX;    const float* w1r=Wih+(long)(j0+1)*DKX;
    const float* w0z=Wih+(long)(HH+j0+0)*DKX; const float* w1z=Wih+(long)(HH+j0+1)*DKX;
    const float* w0n=Wih+(long)(2*HH+j0)*DKX; const float* w1n=Wih+(long)(2*HH+j0+1)*DKX;
    #pragma unroll 2
    for (int k=0;k<DKX;k+=4){
      float x0=xb[k],x1=xb[k+1],x2=xb[k+2],x3=xb[k+3];
      float4 w;
      w=*(const float4*)(w0r+k); xr[0]+=w.x*x0+w.y*x1+w.z*x2+w.w*x3;
      w=*(const float4*)(w1r+k); xr[1]+=w.x*x0+w.y*x1+w.z*x2+w.w*x3;
      w=*(const float4*)(w0z+k); xz[0]+=w.x*x0+w.y*x1+w.z*x2+w.w*x3;
      w=*(const float4*)(w1z+k); xz[1]+=w.x*x0+w.y*x1+w.z*x2+w.w*x3;
      w=*(const float4*)(w0n+k); xn[0]+=w.x*x0+w.y*x1+w.z*x2+w.w*x3;
      w=*(const float4*)(w1n+k); xn[1]+=w.x*x0+w.y*x1+w.z*x2+w.w*x3;
    }
  }
  float hr[2]={0,0},hz[2]={0,0},hn[2]={0,0};
  {
    const float* w0r=Whh+(j0+0)*HH;    const float* w1r=Whh+(j0+1)*HH;
    const float* w0z=Whh+(HH+j0+0)*HH; const float* w1z=Whh+(HH+j0+1)*HH;
    const float* w0n=Whh+(2*HH+j0)*HH; const float* w1n=Whh+(2*HH+j0+1)*HH;
    #pragma unroll 2
    for (int k=0;k<HH;k+=4){
      float h0=hb[k],h1=hb[k+1],h2=hb[k+2],h3=hb[k+3];
      float4 w;
      w=*(const float4*)(w0r+k); hr[0]+=w.x*h0+w.y*h1+w.z*h2+w.w*h3;
      w=*(const float4*)(w1r+k); hr[1]+=w.x*h0+w.y*h1+w.z*h2+w.w*h3;
      w=*(const float4*)(w0z+k); hz[0]+=w.x*h0+w.y*h1+w.z*h2+w.w*h3;
      w=*(const float4*)(w1z+k); hz[1]+=w.x*h0+w.y*h1+w.z*h2+w.w*h3;
      w=*(const float4*)(w0n+k); hn[0]+=w.x*h0+w.y*h1+w.z*h2+w.w*h3;
      w=*(const float4*)(w1n+k); hn[1]+=w.x*h0+w.y*h1+w.z*h2+w.w*h3;
    }
  }
  #pragma unroll
  for (int jj=0;jj<2;jj++){
    int j=j0+jj;
    float ir=xr[jj]+bih[j], iz=xz[jj]+bih[HH+j], in_=xn[jj]+bih[2*HH+j];
    float gr=hr[jj]+bhh[j], gz=hz[jj]+bhh[HH+j], gn=hn[jj]+bhh[2*HH+j];
    float r=sigf(ir+gr), z=sigf(iz+gz);
    float n=tanh_acc(in_+r*gn);
    hnext[b*HH+j]=(1.f-z)*n+z*hb[j];
  }
}

__global__ void k_qw(const float* __restrict__ queryW,int parn){
  int b=blockIdx.y;
  int n=blockIdx.x*8+(threadIdx.x>>5);
  int lane=threadIdx.x&31;
  const float* h=g_dech[parn]+b*HH;
  const float* w=queryW+n*HH;
  float acc=0;
  for (int k=lane;k<HH;k+=32) acc+=h[k]*w[k];
  acc=warp_sum(acc);
  if (lane==0) g_qW[b*HH+n]=acc;
}

__global__ void k_scores(const float* __restrict__ energyW,const int* __restrict__ mask){
  __shared__ float sq[HH];
  __shared__ float se[HH];
  int b=blockIdx.y, tid=threadIdx.x;
  for (int k=tid;k<HH;k+=256){ sq[k]=g_qW[b*HH+k]; se[k]=energyW[k]; }
  __syncthreads();
  int s=blockIdx.x*8+(tid>>5);
  int lane=tid&31;
  if (s<SS){
    const float* pk=g_PK+((long)b*SS+s)*HH;
    float acc=0;
    for (int k=lane;k<HH;k+=32) acc+=se[k]*tanh_acc(sq[k]+pk[k]);
    acc=warp_sum(acc);
    if (lane==0) g_scores[b*SS+s]=(mask[b*SS+s]==0)?-1e30f:acc;
  }
}

__global__ void k_softmax_s(){
  int b=blockIdx.x, tid=threadIdx.x;
  __shared__ float red[256];
  const float* sc=g_scores+b*SS;
  float m=-1e30f;
  for (int s=tid;s<SS;s+=256) m=fmaxf(m,sc[s]);
  red[tid]=m; __syncthreads();
  for (int st=128;st;st>>=1){ if(tid<st) red[tid]=fmaxf(red[tid],red[tid+st]); __syncthreads(); }
  m=red[0]; __syncthreads();
  float sum=0;
  for (int s=tid;s<SS;s+=256) sum+=__expf(sc[s]-m);
  red[tid]=sum; __syncthreads();
  for (int st=128;st;st>>=1){ if(tid<st) red[tid]+=red[tid+st]; __syncthreads(); }
  float inv=__fdividef(1.f,red[0]);
  for (int s=tid;s<SS;s+=256) g_alphas[b*SS+s]=__expf(sc[s]-m)*inv;
}

__global__ void k_context(){
  __shared__ float sal[SS];
  int b=blockIdx.y, tid=threadIdx.x;
  for (int s=tid;s<SS;s+=256) sal[s]=g_alphas[b*SS+s];
  __syncthreads();
  int d=blockIdx.x*256+tid;
  const float* eh=g_EH+(long)b*SS*2*HH+d;
  float acc=0;
  #pragma unroll 4
  for (int s=0;s<SS;s++) acc+=sal[s]*eh[(long)s*2*HH];
  g_context[b*2*HH+d]=acc;
}

__global__ void k_ch(const float* __restrict__ chW,int parn){
  int b=blockIdx.y;
  int n=blockIdx.x*8+(threadIdx.x>>5);
  int lane=threadIdx.x&31;
  const float* q=g_dech[parn]+b*HH;
  const float* c=g_context+b*2*HH;
  const float* w=chW+(long)n*3*HH;
  float acc=0;
  for (int k=lane;k<HH;k+=32) acc+=q[k]*w[k];
  for (int k=lane;k<2*HH;k+=32) acc+=c[k]*w[HH+k];
  acc=warp_sum(acc);
  if (lane==0) g_chvec[b*HH+n]=tanh_acc(acc);
}

__global__ void k_gp(const float* __restrict__ genpW,const float* __restrict__ genpb,int parn,int t){
  int b=blockIdx.x, tid=threadIdx.x;
  __shared__ float red[256];
  float acc=0;
  for (int k=tid;k<3*HH+EE;k+=256){
    float v;
    if (k<2*HH) v=g_context[b*2*HH+k];
    else if (k<3*HH) v=g_dech[parn][b*HH+(k-2*HH)];
    else v=g_pe[(t*BB+b)*EE+(k-3*HH)];
    acc+=v*genpW[k];
  }
  red[tid]=acc; __syncthreads();
  for (int st=128;st;st>>=1){ if(tid<st) red[tid]+=red[tid+st]; __syncthreads(); }
  if (tid==0) g_gp[b]=sigf(red[0]+genpb[0]);
}

__global__ void k_redmax(){
  int b=blockIdx.x, tid=threadIdx.x;
  __shared__ float red[256];
  const float* lg=g_logits+(long)b*VV;
  float m=-1e30f;
  for (int v=tid;v<VV;v+=256) m=fmaxf(m,lg[v]);
  red[tid]=m; __syncthreads();
  for (int st=128;st;st>>=1){ if(tid<st) red[tid]=fmaxf(red[tid],red[tid+st]); __syncthreads(); }
  m=red[0]; __syncthreads();
  float sum=0;
  for (int v=tid;v<VV;v+=256) sum+=__expf(lg[v]-m);
  red[tid]=sum; __syncthreads();
  for (int st=128;st;st>>=1){ if(tid<st) red[tid]+=red[tid+st]; __syncthreads(); }
  if (tid==0){ g_vmax[b]=m; g_vinv[b]=__fdividef(1.f,red[0]); }
}

__global__ void k_write(float* __restrict__ out,int t){
  long i=(long)blockIdx.x*256+threadIdx.x;
  if (i>=(long)BB*VV) return;
  int b=(int)(i/VV), v=(int)(i%VV);
  float p=__expf(g_logits[i]-g_vmax[b])*g_vinv[b];
  out[(long)b*LL*VV+(long)t*VV+v]=g_gp[b]*p;
}

__global__ void k_scatter(float* __restrict__ out,const int* __restrict__ src,int t){
  int i=blockIdx.x*256+threadIdx.x;
  if (i>=BB*SS) return;
  int b=i/SS, s=i%SS;
  float val=(1.f-g_gp[b])*g_alphas[i];
  atomicAdd(&out[(long)b*LL*VV+(long)t*VV+src[i]],val);
}

extern "C" void kernel_launch(void* const* d_in, const int* in_sizes, int n_in,
                              void* d_out, int out_size){
  int w=(in_sizes[5]==1)?6:5;
  const int* src =(const int*)d_in[0];
  const int* trg =(const int*)d_in[1];
  const int* user=(const int*)d_in[2];
  const int* prod=(const int*)d_in[3];
  const int* mask=(const int*)d_in[4];
  const float* embW  =(const float*)d_in[w+0];
  const float* userW =(const float*)d_in[w+1];
  const float* prodW =(const float*)d_in[w+2];
  const float* WihF  =(const float*)d_in[w+3];
  const float* WhhF  =(const float*)d_in[w+4];
  const float* bihF  =(const float*)d_in[w+5];
  const float* bhhF  =(const float*)d_in[w+6];
  const float* WihB  =(const float*)d_in[w+7];
  const float* WhhB  =(const float*)d_in[w+8];
  const float* bihB  =(const float*)d_in[w+9];
  const float* bhhB  =(const float*)d_in[w+10];
  const float* initW =(const float*)d_in[w+11];
  const float* initB =(const float*)d_in[w+12];
  const float* keyW  =(const float*)d_in[w+13];
  const float* queryW=(const float*)d_in[w+14];
  const float* energW=(const float*)d_in[w+15];
  const float* dWih  =(const float*)d_in[w+16];
  const float* dWhh  =(const float*)d_in[w+17];
  const float* dbih  =(const float*)d_in[w+18];
  const float* dbhh  =(const float*)d_in[w+19];
  const float* chW   =(const float*)d_in[w+20];
  const float* genpW =(const float*)d_in[w+21];
  const float* genpb =(const float*)d_in[w+22];
  const float* genW  =(const float*)d_in[w+23];
  float* out=(float*)d_out;

  float *pX,*pGiF,*pGiB,*pEH,*pPK,*pCh,*pLog;
  cudaGetSymbolAddress((void**)&pX,   g_x);
  cudaGetSymbolAddress((void**)&pGiF, g_gi_f);
  cudaGetSymbolAddress((void**)&pGiB, g_gi_b);
  cudaGetSymbolAddress((void**)&pEH,  g_EH);
  cudaGetSymbolAddress((void**)&pPK,  g_PK);
  cudaGetSymbolAddress((void**)&pCh,  g_chvec);
  cudaGetSymbolAddress((void**)&pLog, g_logits);

  cudaFuncSetAttribute(k_enc_step, cudaFuncAttributeMaxDynamicSharedMemorySize, SMEM_ENC);
  cudaFuncSetAttribute(k_dec_step, cudaFuncAttributeMaxDynamicSharedMemorySize, SMEM_DEC);

  k_embed<<<1024,256>>>(src,trg,user,prod,embW,userW,prodW);

  // gi_f = x @ WihF^T + bihF ; gi_b = x @ WihB^T + bihB   (M=12800, N=1536, K=256)
  {
    dim3 g(G3/64, (SS*BB)/64);
    gemm_atb<64,64,32,4,4><<<g,256>>>(pX, WihF, bihF, pGiF, SS*BB, G3, EE);
    gemm_atb<64,64,32,4,4><<<g,256>>>(pX, WihB, bihB, pGiB, SS*BB, G3, EE);
  }

  for (int s=0;s<SS;s++)
    k_enc_step<<<128,128,SMEM_ENC>>>(s, s&1, WhhF,bhhF,WhhB,bhhB);

  k_postenc<<<2048,256>>>();

  // proj_key = EH @ keyW^T   (M=12800, N=512, K=1024)
  {
    dim3 g(HH/64, (SS*BB)/64);
    gemm_atb<64,64,32,4,4><<<g,256>>>(pEH, keyW, nullptr, pPK, SS*BB, HH, 2*HH);
  }

  k_hidden<<<dim3(HH/8,BB),256>>>(initW, initB);

  for (int t=0;t<LL;t++){
    int par=t&1;
    k_dec_step<<<64,128,SMEM_DEC>>>(t,par,dWih,dWhh,dbih,dbhh);
    k_qw<<<dim3(HH/8,BB),256>>>(queryW, par^1);
    k_scores<<<dim3(SS/8,BB),256>>>(energW, mask);
    k_softmax_s<<<BB,256>>>();
    k_context<<<dim3(2*HH/256,BB),256>>>();
    k_ch<<<dim3(HH/8,BB),256>>>(chW, par^1);
    k_gp<<<BB,256>>>(genpW, genpb, par^1, t);
    // logits = ch @ genW^T  (M=32, N=50000, K=512)
    gemm_atb<32,128,32,4,4><<<dim3((VV+127)/128,1),256>>>(pCh, genW, nullptr, pLog, BB, VV, HH);
    k_redmax<<<BB,256>>>();
    k_write<<<(int)(((long)BB*VV+255)/256),256>>>(out, t);
    k_scatter<<<(BB*SS+255)/256,256>>>(out, src, t);
  }
}

// round 4
// speedup vs baseline: 1.0751x; 1.0751x over previous
#include <cuda_runtime.h>
#include <cuda_bf16.h>

#define BB 32
#define SS 400
#define LL 50
#define EE 256
#define HH 512
#define AD 64
#define VV 50000
#define G3 (3*HH)
#define DKX (EE+HH+2*AD)

__device__ float g_x[SS*BB*EE];
__device__ float g_gi_f[SS*BB*G3];
__device__ float g_gi_b[SS*BB*G3];
__device__ float g_hs_f[SS*BB*HH];
__device__ float g_hs_b[SS*BB*HH];
__device__ float g_h[2][2][BB*HH];
__device__ float g_EH[(long)BB*SS*2*HH];
__device__ float g_PK[(long)BB*SS*HH];
__device__ float g_encfin[BB*2*HH];
__device__ float g_pe[LL*BB*EE];
__device__ float g_up[BB*2*AD];
__device__ float g_dech[2][BB*HH];
__device__ float g_chvec[BB*HH];
__device__ float g_qW[BB*HH];
__device__ float g_scores[BB*SS];
__device__ float g_alphas[BB*SS];
__device__ float g_context[BB*2*HH];
__device__ float g_logits[BB*VV];
__device__ float g_gp[BB];
__device__ unsigned g_bar_count;
__device__ unsigned g_bar_gen;

__device__ __forceinline__ float warp_sum(float v){
  #pragma unroll
  for (int o=16;o;o>>=1) v += __shfl_xor_sync(0xffffffffu,v,o);
  return v;
}
__device__ __forceinline__ float sigf(float x){ return __fdividef(1.f,1.f+__expf(-x)); }
__device__ __forceinline__ float tanh_acc(float x){
  float ax=fabsf(x), e=__expf(-2.f*ax);
  float r=__fdividef(1.f-e,1.f+e);
  return (x<0.f)?-r:r;
}

__global__ void k_embed(const int* __restrict__ src,const int* __restrict__ trg,
                        const int* __restrict__ user,const int* __restrict__ prod,
                        const float* __restrict__ embW,const float* __restrict__ userW,
                        const float* __restrict__ prodW){
  if (blockIdx.x==0 && threadIdx.x==0){ g_bar_count=0u; g_bar_gen=0u; }
  int t0=blockIdx.x*blockDim.x+threadIdx.x, st=gridDim.x*blockDim.x;
  for (int i=t0;i<SS*BB*EE;i+=st){
    int e=i%EE, sb=i/EE, b=sb%BB, s=sb/BB;
    g_x[i]=embW[(long)src[b*SS+s]*EE+e];
  }
  for (int i=t0;i<LL*BB*EE;i+=st){
    int e=i%EE, tb=i/EE, b=tb%BB, t=tb/BB;
    int tok=(t==0)?1:trg[b*LL+t-1];
    g_pe[i]=embW[(long)tok*EE+e];
  }
  for (int i=t0;i<BB*2*AD;i+=st){
    int k=i%(2*AD), b=i/(2*AD);
    g_up[i]=(k<AD)?userW[(long)user[b]*AD+k]:prodW[(long)prod[b]*AD+(k-AD)];
  }
  for (int i=t0;i<2*BB*HH;i+=st){
    int d=i/(BB*HH);
    g_h[d][0][i-d*BB*HH]=0.f;
  }
}

template<int BM,int BN,int BK,int TM,int TN>
__global__ void gemm_atb(const float* __restrict__ A,const float* __restrict__ W,
                         const float* __restrict__ bias,float* __restrict__ C,
                         int M,int N,int K){
  constexpr int THREADS=(BM/TM)*(BN/TN);
  __shared__ float As[BK][BM+1];
  __shared__ float Ws[BK][BN+1];
  int m0=blockIdx.y*BM, n0=blockIdx.x*BN, tid=threadIdx.x;
  int tn=tid%(BN/TN), tm=tid/(BN/TN);
  float acc[TM][TN];
  #pragma unroll
  for (int i=0;i<TM;i++)
    #pragma unroll
    for (int j=0;j<TN;j++) acc[i][j]=0.f;
  for (int k0=0;k0<K;k0+=BK){
    for (int i=tid;i<BM*BK;i+=THREADS){
      int r=i/BK,c=i%BK; int m=m0+r;
      As[c][r]=(m<M)?A[(long)m*K+k0+c]:0.f;
    }
    for (int i=tid;i<BN*BK;i+=THREADS){
      int r=i/BK,c=i%BK; int n=n0+r;
      Ws[c][r]=(n<N)?W[(long)n*K+k0+c]:0.f;
    }
    __syncthreads();
    #pragma unroll
    for (int k=0;k<BK;k++){
      float a[TM],w[TN];
      #pragma unroll
      for (int i=0;i<TM;i++) a[i]=As[k][tm*TM+i];
      #pragma unroll
      for (int j=0;j<TN;j++) w[j]=Ws[k][tn*TN+j];
      #pragma unroll
      for (int i=0;i<TM;i++)
        #pragma unroll
        for (int j=0;j<TN;j++) acc[i][j]+=a[i]*w[j];
    }
    __syncthreads();
  }
  #pragma unroll
  for (int i=0;i<TM;i++){
    int m=m0+tm*TM+i; if(m>=M) continue;
    #pragma unroll
    for (int j=0;j<TN;j++){
      int n=n0+tn*TN+j; if(n>=N) continue;
      C[(long)m*N+n]=acc[i][j]+(bias?bias[n]:0.f);
    }
  }
}

// ---------------- persistent encoder: one launch, 400 steps, grid barrier ----------------
#define ENC_BLOCKS 128
#define SMEM_ENC (BB*(HH+4)*4)
__global__ void __launch_bounds__(256,1) k_enc_persist(
                           const float* __restrict__ WhhF,const float* __restrict__ bhhF,
                           const float* __restrict__ WhhB,const float* __restrict__ bhhB){
  extern __shared__ float hs[];   // 32 x 516
  int dir=blockIdx.x>>6, chunk=blockIdx.x&63;
  const float* Whh=dir?WhhB:WhhF;
  const float* bhh=dir?bhhB:bhhF;
  const float* gi =dir?g_gi_b:g_gi_f;
  float* hout =dir?g_hs_b:g_hs_f;
  int tid=threadIdx.x;
  int b=tid&31, jl=tid>>5;       // jl 0..7
  int j=chunk*8+jl;              // 0..511
  const float* wr=Whh+(long)j*HH;
  const float* wz=Whh+(long)(HH+j)*HH;
  const float* wn=Whh+(long)(2*HH+j)*HH;
  float br=bhh[j], bz=bhh[HH+j], bn=bhh[2*HH+j];
  unsigned gen_target=0;

  for (int s=0;s<SS;s++){
    int par=s&1;
    const float* hprev=g_h[dir][par];
    float* hnext=g_h[dir][par^1];
    int sx=dir?(SS-1-s):s;
    // stage hprev -> smem (L2 path; L1 may hold stale lines from 2 steps ago)
    for (int i=tid;i<BB*HH/4;i+=256){
      int bb=i>>7, k=(i&127)<<2;
      float4 v=__ldcg(((const float4*)hprev)+i);
      *(float4*)(hs+bb*(HH+4)+k)=v;
    }
    __syncthreads();
    const float* hb=hs+b*(HH+4);
    float ar=0,az=0,an=0;
    #pragma unroll 4
    for (int k=0;k<HH;k+=4){
      float4 h4=*(const float4*)(hb+k);
      float4 w;
      w=*(const float4*)(wr+k); ar+=w.x*h4.x+w.y*h4.y+w.z*h4.z+w.w*h4.w;
      w=*(const float4*)(wz+k); az+=w.x*h4.x+w.y*h4.y+w.z*h4.z+w.w*h4.w;
      w=*(const float4*)(wn+k); an+=w.x*h4.x+w.y*h4.y+w.z*h4.z+w.w*h4.w;
    }
    long gio=((long)sx*BB+b)*G3;
    float ir=gi[gio+j], iz=gi[gio+HH+j], in_=gi[gio+2*HH+j];
    float r=sigf(ir+ar+br), z=sigf(iz+az+bz);
    float n=tanh_acc(in_+r*(an+bn));
    float hv=(1.f-z)*n+z*hb[j];
    __stcg(&hnext[b*HH+j],hv);
    hout[((long)sx*BB+b)*HH+j]=hv;
    __syncthreads();            // all threads done with hs + stores issued
    if (s<SS-1){
      __threadfence();
      if (tid==0){
        gen_target++;
        unsigned v=atomicAdd(&g_bar_count,1u);
        if (v==ENC_BLOCKS-1){
          atomicExch(&g_bar_count,0u);
          __threadfence();
          atomicAdd(&g_bar_gen,1u);
        } else {
          while (*((volatile unsigned*)&g_bar_gen) < gen_target) __nanosleep(64);
        }
        __threadfence();
      }
      __syncthreads();
    } else {
      if (tid==0) gen_target++;
    }
  }
}

__global__ void k_postenc(){
  int t0=blockIdx.x*blockDim.x+threadIdx.x, st=gridDim.x*blockDim.x;
  for (int i=t0;i<BB*2*HH;i+=st){
    int b=i/(2*HH), k=i%(2*HH);
    g_encfin[i]=(k<HH)?g_hs_f[((long)399*BB+b)*HH+k]:g_hs_b[((long)0*BB+b)*HH+(k-HH)];
  }
  for (long i=t0;i<(long)BB*SS*2*HH;i+=st){
    int d=(int)(i%(2*HH));
    long bs=i/(2*HH);
    int s=(int)(bs%SS), b=(int)(bs/SS);
    g_EH[i]=(d<HH)?g_hs_f[((long)s*BB+b)*HH+d]:g_hs_b[((long)s*BB+b)*HH+(d-HH)];
  }
}

__global__ void k_hidden(const float* __restrict__ initW,const float* __restrict__ initB){
  int b=blockIdx.y;
  int n=blockIdx.x*8+(threadIdx.x>>5);
  int lane=threadIdx.x&31;
  const float* f=g_encfin+b*2*HH;
  const float* w=initW+n*2*HH;
  float acc=0;
  for (int k=lane;k<2*HH;k+=32) acc+=f[k]*w[k];
  acc=warp_sum(acc);
  if (lane==0){
    float hv=tanh_acc(acc+initB[n]);
    g_dech[0][b*HH+n]=hv;
    g_chvec[b*HH+n]=hv;
  }
}

// ---------------- decoder GRU step: 128 blocks x 128 thr, 1 j per thread ----------------
#define SMEM_DEC ((BB*(HH+4)+BB*(DKX+4))*4)
__global__ void __launch_bounds__(128,1) k_dec_step(int t,int par,
                           const float* __restrict__ Wih,const float* __restrict__ Whh,
                           const float* __restrict__ bih,const float* __restrict__ bhh){
  extern __shared__ float sm[];
  float* hs=sm;                       // 32 x 516
  float* xs=sm+BB*(HH+4);             // 32 x 900
  int tid=threadIdx.x;
  const float* hprev=g_dech[par];
  float* hnext=g_dech[par^1];
  for (int i=tid;i<BB*HH/4;i+=128){
    int bb=i>>7, k=(i&127)<<2;
    *(float4*)(hs+bb*(HH+4)+k)=((const float4*)hprev)[i];
  }
  for (int i=tid;i<BB*DKX;i+=128){
    int b=i/DKX, k=i%DKX; float v;
    if (k<EE) v=g_pe[(t*BB+b)*EE+k];
    else if (k<EE+HH) v=g_chvec[b*HH+(k-EE)];
    else v=g_up[b*2*AD+(k-EE-HH)];
    xs[b*(DKX+4)+k]=v;
  }
  __syncthreads();
  int b=tid&31, jl=tid>>5;           // 0..3
  int j=blockIdx.x*4+jl;             // 0..511
  const float* hb=hs+b*(HH+4);
  const float* xb=xs+b*(DKX+4);
  float xr=0,xz=0,xn=0;
  {
    const float* w0=Wih+(long)j*DKX;
    const float* w1=Wih+(long)(HH+j)*DKX;
    const float* w2=Wih+(long)(2*HH+j)*DKX;
    #pragma unroll 4
    for (int k=0;k<DKX;k+=4){
      float4 x4=*(const float4*)(xb+k);
      float4 w;
      w=*(const float4*)(w0+k); xr+=w.x*x4.x+w.y*x4.y+w.z*x4.z+w.w*x4.w;
      w=*(const float4*)(w1+k); xz+=w.x*x4.x+w.y*x4.y+w.z*x4.z+w.w*x4.w;
      w=*(const float4*)(w2+k); xn+=w.x*x4.x+w.y*x4.y+w.z*x4.z+w.w*x4.w;
    }
  }
  float hr=0,hz=0,hn=0;
  {
    const float* w0=Whh+(long)j*HH;
    const float* w1=Whh+(long)(HH+j)*HH;
    const float* w2=Whh+(long)(2*HH+j)*HH;
    #pragma unroll 4
    for (int k=0;k<HH;k+=4){
      float4 h4=*(const float4*)(hb+k);
      float4 w;
      w=*(const float4*)(w0+k); hr+=w.x*h4.x+w.y*h4.y+w.z*h4.z+w.w*h4.w;
      w=*(const float4*)(w1+k); hz+=w.x*h4.x+w.y*h4.y+w.z*h4.z+w.w*h4.w;
      w=*(const float4*)(w2+k); hn+=w.x*h4.x+w.y*h4.y+w.z*h4.z+w.w*h4.w;
    }
  }
  float ir=xr+bih[j], iz=xz+bih[HH+j], in_=xn+bih[2*HH+j];
  float gr=hr+bhh[j], gz=hz+bhh[HH+j], gn=hn+bhh[2*HH+j];
  float r=sigf(ir+gr), z=sigf(iz+gz);
  float n=tanh_acc(in_+r*gn);
  hnext[b*HH+j]=(1.f-z)*n+z*hb[j];
}

__global__ void k_qw(const float* __restrict__ queryW,int parn){
  int b=blockIdx.y;
  int n=blockIdx.x*8+(threadIdx.x>>5);
  int lane=threadIdx.x&31;
  const float* h=g_dech[parn]+b*HH;
  const float* w=queryW+n*HH;
  float acc=0;
  for (int k=lane;k<HH;k+=32) acc+=h[k]*w[k];
  acc=warp_sum(acc);
  if (lane==0) g_qW[b*HH+n]=acc;
}

__global__ void k_scores(const float* __restrict__ energyW,const int* __restrict__ mask){
  __shared__ float sq[HH];
  __shared__ float se[HH];
  int b=blockIdx.y, tid=threadIdx.x;
  for (int k=tid;k<HH;k+=256){ sq[k]=g_qW[b*HH+k]; se[k]=energyW[k]; }
  __syncthreads();
  int s=blockIdx.x*8+(tid>>5);
  int lane=tid&31;
  if (s<SS){
    const float* pk=g_PK+((long)b*SS+s)*HH;
    float acc=0;
    for (int k=lane;k<HH;k+=32) acc+=se[k]*tanh_acc(sq[k]+pk[k]);
    acc=warp_sum(acc);
    if (lane==0) g_scores[b*SS+s]=(mask[b*SS+s]==0)?-1e30f:acc;
  }
}

__global__ void k_softmax_s(){
  int b=blockIdx.x, tid=threadIdx.x;
  __shared__ float red[256];
  const float* sc=g_scores+b*SS;
  float m=-1e30f;
  for (int s=tid;s<SS;s+=256) m=fmaxf(m,sc[s]);
  red[tid]=m; __syncthreads();
  for (int st=128;st;st>>=1){ if(tid<st) red[tid]=fmaxf(red[tid],red[tid+st]); __syncthreads(); }
  m=red[0]; __syncthreads();
  float sum=0;
  for (int s=tid;s<SS;s+=256) sum+=__expf(sc[s]-m);
  red[tid]=sum; __syncthreads();
  for (int st=128;st;st>>=1){ if(tid<st) red[tid]+=red[tid+st]; __syncthreads(); }
  float inv=__fdividef(1.f,red[0]);
  for (int s=tid;s<SS;s+=256) g_alphas[b*SS+s]=__expf(sc[s]-m)*inv;
}

__global__ void k_context(){
  __shared__ float sal[SS];
  int b=blockIdx.y, tid=threadIdx.x;
  for (int s=tid;s<SS;s+=256) sal[s]=g_alphas[b*SS+s];
  __syncthreads();
  int d=blockIdx.x*256+tid;
  const float* eh=g_EH+(long)b*SS*2*HH+d;
  float acc=0;
  #pragma unroll 4
  for (int s=0;s<SS;s++) acc+=sal[s]*eh[(long)s*2*HH];
  g_context[b*2*HH+d]=acc;
}

__global__ void k_ch(const float* __restrict__ chW,int parn){
  int b=blockIdx.y;
  int n=blockIdx.x*8+(threadIdx.x>>5);
  int lane=threadIdx.x&31;
  const float* q=g_dech[parn]+b*HH;
  const float* c=g_context+b*2*HH;
  const float* w=chW+(long)n*3*HH;
  float acc=0;
  for (int k=lane;k<HH;k+=32) acc+=q[k]*w[k];
  for (int k=lane;k<2*HH;k+=32) acc+=c[k]*w[HH+k];
  acc=warp_sum(acc);
  if (lane==0) g_chvec[b*HH+n]=tanh_acc(acc);
}

__global__ void k_gp(const float* __restrict__ genpW,const float* __restrict__ genpb,int parn,int t){
  int b=blockIdx.x, tid=threadIdx.x;
  __shared__ float red[256];
  float acc=0;
  for (int k=tid;k<3*HH+EE;k+=256){
    float v;
    if (k<2*HH) v=g_context[b*2*HH+k];
    else if (k<3*HH) v=g_dech[parn][b*HH+(k-2*HH)];
    else v=g_pe[(t*BB+b)*EE+(k-3*HH)];
    acc+=v*genpW[k];
  }
  red[tid]=acc; __syncthreads();
  for (int st=128;st;st>>=1){ if(tid<st) red[tid]+=red[tid+st]; __syncthreads(); }
  if (tid==0) g_gp[b]=sigf(red[0]+genpb[0]);
}

// fused vocab softmax + output write (3 L2-resident passes)
__global__ void k_vocab_out(float* __restrict__ out,int t){
  int b=blockIdx.x, tid=threadIdx.x;  // 1024 threads
  __shared__ float red[1024];
  const float* lg=g_logits+(long)b*VV;
  float m=-1e30f;
  for (int v=tid*4;v<VV;v+=4096){
    float4 x=*(const float4*)(lg+v);
    m=fmaxf(m,fmaxf(fmaxf(x.x,x.y),fmaxf(x.z,x.w)));
  }
  red[tid]=m; __syncthreads();
  for (int st=512;st;st>>=1){ if(tid<st) red[tid]=fmaxf(red[tid],red[tid+st]); __syncthreads(); }
  m=red[0]; __syncthreads();
  float sum=0;
  for (int v=tid*4;v<VV;v+=4096){
    float4 x=*(const float4*)(lg+v);
    sum+=__expf(x.x-m)+__expf(x.y-m)+__expf(x.z-m)+__expf(x.w-m);
  }
  red[tid]=sum; __syncthreads();
  for (int st=512;st;st>>=1){ if(tid<st) red[tid]+=red[tid+st]; __syncthreads(); }
  float gp=g_gp[b];
  float inv=__fdividef(gp,red[0]);
  float* ob=out+(long)b*LL*VV+(long)t*VV;
  for (int v=tid*4;v<VV;v+=4096){
    float4 x=*(const float4*)(lg+v);
    float4 y;
    y.x=__expf(x.x-m)*inv; y.y=__expf(x.y-m)*inv;
    y.z=__expf(x.z-m)*inv; y.w=__expf(x.w-m)*inv;
    *(float4*)(ob+v)=y;
  }
}

__global__ void k_scatter(float* __restrict__ out,const int* __restrict__ src,int t){
  int i=blockIdx.x*256+threadIdx.x;
  if (i>=BB*SS) return;
  int b=i/SS, s=i%SS;
  float val=(1.f-g_gp[b])*g_alphas[i];
  atomicAdd(&out[(long)b*LL*VV+(long)t*VV+src[i]],val);
}

extern "C" void kernel_launch(void* const* d_in, const int* in_sizes, int n_in,
                              void* d_out, int out_size){
  int w=(in_sizes[5]==1)?6:5;
  const int* src =(const int*)d_in[0];
  const int* trg =(const int*)d_in[1];
  const int* user=(const int*)d_in[2];
  const int* prod=(const int*)d_in[3];
  const int* mask=(const int*)d_in[4];
  const float* embW  =(const float*)d_in[w+0];
  const float* userW =(const float*)d_in[w+1];
  const float* prodW =(const float*)d_in[w+2];
  const float* WihF  =(const float*)d_in[w+3];
  const float* WhhF  =(const float*)d_in[w+4];
  const float* bihF  =(const float*)d_in[w+5];
  const float* bhhF  =(const float*)d_in[w+6];
  const float* WihB  =(const float*)d_in[w+7];
  const float* WhhB  =(const float*)d_in[w+8];
  const float* bihB  =(const float*)d_in[w+9];
  const float* bhhB  =(const float*)d_in[w+10];
  const float* initW =(const float*)d_in[w+11];
  const float* initB =(const float*)d_in[w+12];
  const float* keyW  =(const float*)d_in[w+13];
  const float* queryW=(const float*)d_in[w+14];
  const float* energW=(const float*)d_in[w+15];
  const float* dWih  =(const float*)d_in[w+16];
  const float* dWhh  =(const float*)d_in[w+17];
  const float* dbih  =(const float*)d_in[w+18];
  const float* dbhh  =(const float*)d_in[w+19];
  const float* chW   =(const float*)d_in[w+20];
  const float* genpW =(const float*)d_in[w+21];
  const float* genpb =(const float*)d_in[w+22];
  const float* genW  =(const float*)d_in[w+23];
  float* out=(float*)d_out;

  float *pX,*pGiF,*pGiB,*pEH,*pPK,*pCh,*pLog;
  cudaGetSymbolAddress((void**)&pX,   g_x);
  cudaGetSymbolAddress((void**)&pGiF, g_gi_f);
  cudaGetSymbolAddress((void**)&pGiB, g_gi_b);
  cudaGetSymbolAddress((void**)&pEH,  g_EH);
  cudaGetSymbolAddress((void**)&pPK,  g_PK);
  cudaGetSymbolAddress((void**)&pCh,  g_chvec);
  cudaGetSymbolAddress((void**)&pLog, g_logits);

  cudaFuncSetAttribute(k_enc_persist, cudaFuncAttributeMaxDynamicSharedMemorySize, SMEM_ENC);
  cudaFuncSetAttribute(k_dec_step,    cudaFuncAttributeMaxDynamicSharedMemorySize, SMEM_DEC);

  k_embed<<<1024,256>>>(src,trg,user,prod,embW,userW,prodW);

  {
    dim3 g(G3/64, (SS*BB)/64);
    gemm_atb<64,64,32,4,4><<<g,256>>>(pX, WihF, bihF, pGiF, SS*BB, G3, EE);
    gemm_atb<64,64,32,4,4><<<g,256>>>(pX, WihB, bihB, pGiB, SS*BB, G3, EE);
  }

  k_enc_persist<<<ENC_BLOCKS,256,SMEM_ENC>>>(WhhF,bhhF,WhhB,bhhB);

  k_postenc<<<2048,256>>>();

  {
    dim3 g(HH/64, (SS*BB)/64);
    gemm_atb<64,64,32,4,4><<<g,256>>>(pEH, keyW, nullptr, pPK, SS*BB, HH, 2*HH);
  }

  k_hidden<<<dim3(HH/8,BB),256>>>(initW, initB);

  for (int t=0;t<LL;t++){
    int par=t&1;
    k_dec_step<<<128,128,SMEM_DEC>>>(t,par,dWih,dWhh,dbih,dbhh);
    k_qw<<<dim3(HH/8,BB),256>>>(queryW, par^1);
    k_scores<<<dim3(SS/8,BB),256>>>(energW, mask);
    k_softmax_s<<<BB,256>>>();
    k_context<<<dim3(2*HH/256,BB),256>>>();
    k_ch<<<dim3(HH/8,BB),256>>>(chW, par^1);
    k_gp<<<BB,256>>>(genpW, genpb, par^1, t);
    gemm_atb<32,128,32,4,4><<<dim3((VV+127)/128,1),256>>>(pCh, genW, nullptr, pLog, BB, VV, HH);
    k_vocab_out<<<BB,1024>>>(out, t);
    k_scatter<<<(BB*SS+255)/256,256>>>(out, src, t);
  }
}

// round 5
// speedup vs baseline: 1.5037x; 1.3986x over previous
#include <cuda_runtime.h>
#include <cuda_bf16.h>

#define BB 32
#define SS 400
#define LL 50
#define EE 256
#define HH 512
#define AD 64
#define VV 50000
#define G3 (3*HH)
#define DKX (EE+HH+2*AD)

__device__ float g_x[SS*BB*EE];
__device__ float g_gi_f[SS*BB*G3];
__device__ float g_gi_b[SS*BB*G3];
__device__ float g_hs_f[SS*BB*HH];
__device__ float g_hs_b[SS*BB*HH];
__device__ float g_h[2][2][BB*HH];
__device__ float g_EH[(long)BB*SS*2*HH];
__device__ float g_PK[(long)BB*SS*HH];
__device__ float g_encfin[BB*2*HH];
__device__ float g_pe[LL*BB*EE];
__device__ float g_up[BB*2*AD];
__device__ float g_dech[2][BB*HH];
__device__ float g_chvec[BB*HH];
__device__ float g_qW[BB*HH];
__device__ float g_scores[BB*SS];
__device__ float g_alphas[BB*SS];
__device__ float g_context[BB*2*HH];
__device__ float g_logits[BB*VV];
__device__ float g_gp[BB];
__device__ unsigned g_bar_count;
__device__ unsigned g_bar_gen;

__device__ __forceinline__ float warp_sum(float v){
  #pragma unroll
  for (int o=16;o;o>>=1) v += __shfl_xor_sync(0xffffffffu,v,o);
  return v;
}
__device__ __forceinline__ float sigf(float x){ return __fdividef(1.f,1.f+__expf(-x)); }
__device__ __forceinline__ float tanh_acc(float x){
  float ax=fabsf(x), e=__expf(-2.f*ax);
  float r=__fdividef(1.f-e,1.f+e);
  return (x<0.f)?-r:r;
}

// ---- fence-free barrier primitives (no CCTL.IVALL -> L1D stays warm) ----
__device__ __forceinline__ unsigned ld_acq(const unsigned* p){
  unsigned v;
  asm volatile("ld.acquire.gpu.global.u32 %0,[%1];":"=r"(v):"l"(p):"memory");
  return v;
}
__device__ __forceinline__ unsigned atom_add_acqrel(unsigned* p, unsigned v){
  unsigned o;
  asm volatile("atom.acq_rel.gpu.global.add.u32 %0,[%1],%2;":"=r"(o):"l"(p),"r"(v):"memory");
  return o;
}
__device__ __forceinline__ void red_add_rel(unsigned* p, unsigned v){
  asm volatile("red.release.gpu.global.add.u32 [%0],%1;"::"l"(p),"r"(v):"memory");
}

__global__ void k_embed(const int* __restrict__ src,const int* __restrict__ trg,
                        const int* __restrict__ user,const int* __restrict__ prod,
                        const float* __restrict__ embW,const float* __restrict__ userW,
                        const float* __restrict__ prodW){
  if (blockIdx.x==0 && threadIdx.x==0){ g_bar_count=0u; g_bar_gen=0u; }
  int t0=blockIdx.x*blockDim.x+threadIdx.x, st=gridDim.x*blockDim.x;
  for (int i=t0;i<SS*BB*EE;i+=st){
    int e=i%EE, sb=i/EE, b=sb%BB, s=sb/BB;
    g_x[i]=embW[(long)src[b*SS+s]*EE+e];
  }
  for (int i=t0;i<LL*BB*EE;i+=st){
    int e=i%EE, tb=i/EE, b=tb%BB, t=tb/BB;
    int tok=(t==0)?1:trg[b*LL+t-1];
    g_pe[i]=embW[(long)tok*EE+e];
  }
  for (int i=t0;i<BB*2*AD;i+=st){
    int k=i%(2*AD), b=i/(2*AD);
    g_up[i]=(k<AD)?userW[(long)user[b]*AD+k]:prodW[(long)prod[b]*AD+(k-AD)];
  }
  for (int i=t0;i<2*BB*HH;i+=st){
    int d=i/(BB*HH);
    g_h[d][0][i-d*BB*HH]=0.f;
  }
}

template<int BM,int BN,int BK,int TM,int TN>
__global__ void gemm_atb(const float* __restrict__ A,const float* __restrict__ W,
                         const float* __restrict__ bias,float* __restrict__ C,
                         int M,int N,int K){
  constexpr int THREADS=(BM/TM)*(BN/TN);
  __shared__ float As[BK][BM+1];
  __shared__ float Ws[BK][BN+1];
  int m0=blockIdx.y*BM, n0=blockIdx.x*BN, tid=threadIdx.x;
  int tn=tid%(BN/TN), tm=tid/(BN/TN);
  float acc[TM][TN];
  #pragma unroll
  for (int i=0;i<TM;i++)
    #pragma unroll
    for (int j=0;j<TN;j++) acc[i][j]=0.f;
  for (int k0=0;k0<K;k0+=BK){
    for (int i=tid;i<BM*BK;i+=THREADS){
      int r=i/BK,c=i%BK; int m=m0+r;
      As[c][r]=(m<M)?A[(long)m*K+k0+c]:0.f;
    }
    for (int i=tid;i<BN*BK;i+=THREADS){
      int r=i/BK,c=i%BK; int n=n0+r;
      Ws[c][r]=(n<N)?W[(long)n*K+k0+c]:0.f;
    }
    __syncthreads();
    #pragma unroll
    for (int k=0;k<BK;k++){
      float a[TM],w[TN];
      #pragma unroll
      for (int i=0;i<TM;i++) a[i]=As[k][tm*TM+i];
      #pragma unroll
      for (int j=0;j<TN;j++) w[j]=Ws[k][tn*TN+j];
      #pragma unroll
      for (int i=0;i<TM;i++)
        #pragma unroll
        for (int j=0;j<TN;j++) acc[i][j]+=a[i]*w[j];
    }
    __syncthreads();
  }
  #pragma unroll
  for (int i=0;i<TM;i++){
    int m=m0+tm*TM+i; if(m>=M) continue;
    #pragma unroll
    for (int j=0;j<TN;j++){
      int n=n0+tn*TN+j; if(n>=N) continue;
      C[(long)m*N+n]=acc[i][j]+(bias?bias[n]:0.f);
    }
  }
}

// ---------------- persistent encoder: one launch, 400 steps, fence-free grid barrier ----------------
#define ENC_BLOCKS 128
#define SMEM_ENC (BB*(HH+4)*4)
__global__ void __launch_bounds__(256,1) k_enc_persist(
                           const float* __restrict__ WhhF,const float* __restrict__ bhhF,
                           const float* __restrict__ WhhB,const float* __restrict__ bhhB){
  extern __shared__ float hs[];   // 32 x 516
  int dir=blockIdx.x>>6, chunk=blockIdx.x&63;
  const float* Whh=dir?WhhB:WhhF;
  const float* bhh=dir?bhhB:bhhF;
  const float* gi =dir?g_gi_b:g_gi_f;
  float* hout =dir?g_hs_b:g_hs_f;
  int tid=threadIdx.x;
  int b=tid&31, jl=tid>>5;       // jl 0..7
  int j=chunk*8+jl;              // 0..511
  const float* wr=Whh+(long)j*HH;
  const float* wz=Whh+(long)(HH+j)*HH;
  const float* wn=Whh+(long)(2*HH+j)*HH;
  float br=bhh[j], bz=bhh[HH+j], bn=bhh[2*HH+j];
  unsigned gen_target=0;

  for (int s=0;s<SS;s++){
    int par=s&1;
    const float* hprev=g_h[dir][par];
    float* hnext=g_h[dir][par^1];
    int sx=dir?(SS-1-s):s;
    // stage hprev -> smem via L2 path (L1 may hold stale lines from 2 steps ago)
    for (int i=tid;i<BB*HH/4;i+=256){
      int bb=i>>7, k=(i&127)<<2;
      float4 v=__ldcg(((const float4*)hprev)+i);
      *(float4*)(hs+bb*(HH+4)+k)=v;
    }
    __syncthreads();
    const float* hb=hs+b*(HH+4);
    float ar=0,az=0,an=0;
    #pragma unroll 4
    for (int k=0;k<HH;k+=4){
      float4 h4=*(const float4*)(hb+k);
      float4 w;
      w=*(const float4*)(wr+k); ar+=w.x*h4.x+w.y*h4.y+w.z*h4.z+w.w*h4.w;
      w=*(const float4*)(wz+k); az+=w.x*h4.x+w.y*h4.y+w.z*h4.z+w.w*h4.w;
      w=*(const float4*)(wn+k); an+=w.x*h4.x+w.y*h4.y+w.z*h4.z+w.w*h4.w;
    }
    long gio=((long)sx*BB+b)*G3;
    float ir=gi[gio+j], iz=gi[gio+HH+j], in_=gi[gio+2*HH+j];
    float r=sigf(ir+ar+br), z=sigf(iz+az+bz);
    float n=tanh_acc(in_+r*(an+bn));
    float hv=(1.f-z)*n+z*hb[j];
    __stcg(&hnext[b*HH+j],hv);
    hout[((long)sx*BB+b)*HH+j]=hv;
    __syncthreads();            // block done with hs; STG.CG issued
    if (s<SS-1){
      if (tid==0){
        gen_target++;
        // acq_rel arrive: releases this block's h stores, acquires peers' on last-arrive
        unsigned v=atom_add_acqrel(&g_bar_count,1u);
        if (v==ENC_BLOCKS-1){
          atomicExch(&g_bar_count,0u);          // relaxed reset (ordered by release below)
          red_add_rel(&g_bar_gen,1u);           // release gen bump
        } else {
          while (ld_acq(&g_bar_gen) < gen_target) __nanosleep(32);
        }
      }
      __syncthreads();
    }
  }
}

__global__ void k_postenc(){
  int t0=blockIdx.x*blockDim.x+threadIdx.x, st=gridDim.x*blockDim.x;
  for (int i=t0;i<BB*2*HH;i+=st){
    int b=i/(2*HH), k=i%(2*HH);
    g_encfin[i]=(k<HH)?g_hs_f[((long)399*BB+b)*HH+k]:g_hs_b[((long)0*BB+b)*HH+(k-HH)];
  }
  for (long i=t0;i<(long)BB*SS*2*HH;i+=st){
    int d=(int)(i%(2*HH));
    long bs=i/(2*HH);
    int s=(int)(bs%SS), b=(int)(bs/SS);
    g_EH[i]=(d<HH)?g_hs_f[((long)s*BB+b)*HH+d]:g_hs_b[((long)s*BB+b)*HH+(d-HH)];
  }
}

__global__ void k_hidden(const float* __restrict__ initW,const float* __restrict__ initB){
  int b=blockIdx.y;
  int n=blockIdx.x*8+(threadIdx.x>>5);
  int lane=threadIdx.x&31;
  const float* f=g_encfin+b*2*HH;
  const float* w=initW+n*2*HH;
  float acc=0;
  for (int k=lane;k<2*HH;k+=32) acc+=f[k]*w[k];
  acc=warp_sum(acc);
  if (lane==0){
    float hv=tanh_acc(acc+initB[n]);
    g_dech[0][b*HH+n]=hv;
    g_chvec[b*HH+n]=hv;
  }
}

// ---------------- decoder GRU step: 128 blocks x 128 thr, 1 j per thread ----------------
#define SMEM_DEC ((BB*(HH+4)+BB*(DKX+4))*4)
__global__ void __launch_bounds__(128,1) k_dec_step(int t,int par,
                           const float* __restrict__ Wih,const float* __restrict__ Whh,
                           const float* __restrict__ bih,const float* __restrict__ bhh){
  extern __shared__ float sm[];
  float* hs=sm;                       // 32 x 516
  float* xs=sm+BB*(HH+4);             // 32 x 900
  int tid=threadIdx.x;
  const float* hprev=g_dech[par];
  float* hnext=g_dech[par^1];
  for (int i=tid;i<BB*HH/4;i+=128){
    int bb=i>>7, k=(i&127)<<2;
    *(float4*)(hs+bb*(HH+4)+k)=((const float4*)hprev)[i];
  }
  for (int i=tid;i<BB*DKX;i+=128){
    int b=i/DKX, k=i%DKX; float v;
    if (k<EE) v=g_pe[(t*BB+b)*EE+k];
    else if (k<EE+HH) v=g_chvec[b*HH+(k-EE)];
    else v=g_up[b*2*AD+(k-EE-HH)];
    xs[b*(DKX+4)+k]=v;
  }
  __syncthreads();
  int b=tid&31, jl=tid>>5;           // 0..3
  int j=blockIdx.x*4+jl;             // 0..511
  const float* hb=hs+b*(HH+4);
  const float* xb=xs+b*(DKX+4);
  float xr=0,xz=0,xn=0;
  {
    const float* w0=Wih+(long)j*DKX;
    const float* w1=Wih+(long)(HH+j)*DKX;
    const float* w2=Wih+(long)(2*HH+j)*DKX;
    #pragma unroll 4
    for (int k=0;k<DKX;k+=4){
      float4 x4=*(const float4*)(xb+k);
      float4 w;
      w=*(const float4*)(w0+k); xr+=w.x*x4.x+w.y*x4.y+w.z*x4.z+w.w*x4.w;
      w=*(const float4*)(w1+k); xz+=w.x*x4.x+w.y*x4.y+w.z*x4.z+w.w*x4.w;
      w=*(const float4*)(w2+k); xn+=w.x*x4.x+w.y*x4.y+w.z*x4.z+w.w*x4.w;
    }
  }
  float hr=0,hz=0,hn=0;
  {
    const float* w0=Whh+(long)j*HH;
    const float* w1=Whh+(long)(HH+j)*HH;
    const float* w2=Whh+(long)(2*HH+j)*HH;
    #pragma unroll 4
    for (int k=0;k<HH;k+=4){
      float4 h4=*(const float4*)(hb+k);
      float4 w;
      w=*(const float4*)(w0+k); hr+=w.x*h4.x+w.y*h4.y+w.z*h4.z+w.w*h4.w;
      w=*(const float4*)(w1+k); hz+=w.x*h4.x+w.y*h4.y+w.z*h4.z+w.w*h4.w;
      w=*(const float4*)(w2+k); hn+=w.x*h4.x+w.y*h4.y+w.z*h4.z+w.w*h4.w;
    }
  }
  float ir=xr+bih[j], iz=xz+bih[HH+j], in_=xn+bih[2*HH+j];
  float gr=hr+bhh[j], gz=hz+bhh[HH+j], gn=hn+bhh[2*HH+j];
  float r=sigf(ir+gr), z=sigf(iz+gz);
  float n=tanh_acc(in_+r*gn);
  hnext[b*HH+j]=(1.f-z)*n+z*hb[j];
}

__global__ void k_qw(const float* __restrict__ queryW,int parn){
  int b=blockIdx.y;
  int n=blockIdx.x*8+(threadIdx.x>>5);
  int lane=threadIdx.x&31;
  const float* h=g_dech[parn]+b*HH;
  const float* w=queryW+n*HH;
  float acc=0;
  for (int k=lane;k<HH;k+=32) acc+=h[k]*w[k];
  acc=warp_sum(acc);
  if (lane==0) g_qW[b*HH+n]=acc;
}

__global__ void k_scores(const float* __restrict__ energyW,const int* __restrict__ mask){
  __shared__ float sq[HH];
  __shared__ float se[HH];
  int b=blockIdx.y, tid=threadIdx.x;
  for (int k=tid;k<HH;k+=256){ sq[k]=g_qW[b*HH+k]; se[k]=energyW[k]; }
  __syncthreads();
  int s=blockIdx.x*8+(tid>>5);
  int lane=tid&31;
  if (s<SS){
    const float* pk=g_PK+((long)b*SS+s)*HH;
    float acc=0;
    for (int k=lane;k<HH;k+=32) acc+=se[k]*tanh_acc(sq[k]+pk[k]);
    acc=warp_sum(acc);
    if (lane==0) g_scores[b*SS+s]=(mask[b*SS+s]==0)?-1e30f:acc;
  }
}

__global__ void k_softmax_s(){
  int b=blockIdx.x, tid=threadIdx.x;
  __shared__ float red[256];
  const float* sc=g_scores+b*SS;
  float m=-1e30f;
  for (int s=tid;s<SS;s+=256) m=fmaxf(m,sc[s]);
  red[tid]=m; __syncthreads();
  for (int st=128;st;st>>=1){ if(tid<st) red[tid]=fmaxf(red[tid],red[tid+st]); __syncthreads(); }
  m=red[0]; __syncthreads();
  float sum=0;
  for (int s=tid;s<SS;s+=256) sum+=__expf(sc[s]-m);
  red[tid]=sum; __syncthreads();
  for (int st=128;st;st>>=1){ if(tid<st) red[tid]+=red[tid+st]; __syncthreads(); }
  float inv=__fdividef(1.f,red[0]);
  for (int s=tid;s<SS;s+=256) g_alphas[b*SS+s]=__expf(sc[s]-m)*inv;
}

__global__ void k_context(){
  __shared__ float sal[SS];
  int b=blockIdx.y, tid=threadIdx.x;
  for (int s=tid;s<SS;s+=256) sal[s]=g_alphas[b*SS+s];
  __syncthreads();
  int d=blockIdx.x*256+tid;
  const float* eh=g_EH+(long)b*SS*2*HH+d;
  float acc=0;
  #pragma unroll 4
  for (int s=0;s<SS;s++) acc+=sal[s]*eh[(long)s*2*HH];
  g_context[b*2*HH+d]=acc;
}

__global__ void k_ch(const float* __restrict__ chW,int parn){
  int b=blockIdx.y;
  int n=blockIdx.x*8+(threadIdx.x>>5);
  int lane=threadIdx.x&31;
  const float* q=g_dech[parn]+b*HH;
  const float* c=g_context+b*2*HH;
  const float* w=chW+(long)n*3*HH;
  float acc=0;
  for (int k=lane;k<HH;k+=32) acc+=q[k]*w[k];
  for (int k=lane;k<2*HH;k+=32) acc+=c[k]*w[HH+k];
  acc=warp_sum(acc);
  if (lane==0) g_chvec[b*HH+n]=tanh_acc(acc);
}

__global__ void k_gp(const float* __restrict__ genpW,const float* __restrict__ genpb,int parn,int t){
  int b=blockIdx.x, tid=threadIdx.x;
  __shared__ float red[256];
  float acc=0;
  for (int k=tid;k<3*HH+EE;k+=256){
    float v;
    if (k<2*HH) v=g_context[b*2*HH+k];
    else if (k<3*HH) v=g_dech[parn][b*HH+(k-2*HH)];
    else v=g_pe[(t*BB+b)*EE+(k-3*HH)];
    acc+=v*genpW[k];
  }
  red[tid]=acc; __syncthreads();
  for (int st=128;st;st>>=1){ if(tid<st) red[tid]+=red[tid+st]; __syncthreads(); }
  if (tid==0) g_gp[b]=sigf(red[0]+genpb[0]);
}

// fused vocab softmax + output write
__global__ void k_vocab_out(float* __restrict__ out,int t){
  int b=blockIdx.x, tid=threadIdx.x;  // 1024 threads
  __shared__ float red[1024];
  const float* lg=g_logits+(long)b*VV;
  float m=-1e30f;
  for (int v=tid*4;v<VV;v+=4096){
    float4 x=*(const float4*)(lg+v);
    m=fmaxf(m,fmaxf(fmaxf(x.x,x.y),fmaxf(x.z,x.w)));
  }
  red[tid]=m; __syncthreads();
  for (int st=512;st;st>>=1){ if(tid<st) red[tid]=fmaxf(red[tid],red[tid+st]); __syncthreads(); }
  m=red[0]; __syncthreads();
  float sum=0;
  for (int v=tid*4;v<VV;v+=4096){
    float4 x=*(const float4*)(lg+v);
    sum+=__expf(x.x-m)+__expf(x.y-m)+__expf(x.z-m)+__expf(x.w-m);
  }
  red[tid]=sum; __syncthreads();
  for (int st=512;st;st>>=1){ if(tid<st) red[tid]+=red[tid+st]; __syncthreads(); }
  float gp=g_gp[b];
  float inv=__fdividef(gp,red[0]);
  float* ob=out+(long)b*LL*VV+(long)t*VV;
  for (int v=tid*4;v<VV;v+=4096){
    float4 x=*(const float4*)(lg+v);
    float4 y;
    y.x=__expf(x.x-m)*inv; y.y=__expf(x.y-m)*inv;
    y.z=__expf(x.z-m)*inv; y.w=__expf(x.w-m)*inv;
    *(float4*)(ob+v)=y;
  }
}

__global__ void k_scatter(float* __restrict__ out,const int* __restrict__ src,int t){
  int i=blockIdx.x*256+threadIdx.x;
  if (i>=BB*SS) return;
  int b=i/SS, s=i%SS;
  float val=(1.f-g_gp[b])*g_alphas[i];
  atomicAdd(&out[(long)b*LL*VV+(long)t*VV+src[i]],val);
}

extern "C" void kernel_launch(void* const* d_in, const int* in_sizes, int n_in,
                              void* d_out, int out_size){
  int w=(in_sizes[5]==1)?6:5;
  const int* src =(const int*)d_in[0];
  const int* trg =(const int*)d_in[1];
  const int* user=(const int*)d_in[2];
  const int* prod=(const int*)d_in[3];
  const int* mask=(const int*)d_in[4];
  const float* embW  =(const float*)d_in[w+0];
  const float* userW =(const float*)d_in[w+1];
  const float* prodW =(const float*)d_in[w+2];
  const float* WihF  =(const float*)d_in[w+3];
  const float* WhhF  =(const float*)d_in[w+4];
  const float* bihF  =(const float*)d_in[w+5];
  const float* bhhF  =(const float*)d_in[w+6];
  const float* WihB  =(const float*)d_in[w+7];
  const float* WhhB  =(const float*)d_in[w+8];
  const float* bihB  =(const float*)d_in[w+9];
  const float* bhhB  =(const float*)d_in[w+10];
  const float* initW =(const float*)d_in[w+11];
  const float* initB =(const float*)d_in[w+12];
  const float* keyW  =(const float*)d_in[w+13];
  const float* queryW=(const float*)d_in[w+14];
  const float* energW=(const float*)d_in[w+15];
  const float* dWih  =(const float*)d_in[w+16];
  const float* dWhh  =(const float*)d_in[w+17];
  const float* dbih  =(const float*)d_in[w+18];
  const float* dbhh  =(const float*)d_in[w+19];
  const float* chW   =(const float*)d_in[w+20];
  const float* genpW =(const float*)d_in[w+21];
  const float* genpb =(const float*)d_in[w+22];
  const float* genW  =(const float*)d_in[w+23];
  float* out=(float*)d_out;

  float *pX,*pGiF,*pGiB,*pEH,*pPK,*pCh,*pLog;
  cudaGetSymbolAddress((void**)&pX,   g_x);
  cudaGetSymbolAddress((void**)&pGiF, g_gi_f);
  cudaGetSymbolAddress((void**)&pGiB, g_gi_b);
  cudaGetSymbolAddress((void**)&pEH,  g_EH);
  cudaGetSymbolAddress((void**)&pPK,  g_PK);
  cudaGetSymbolAddress((void**)&pCh,  g_chvec);
  cudaGetSymbolAddress((void**)&pLog, g_logits);

  cudaFuncSetAttribute(k_enc_persist, cudaFuncAttributeMaxDynamicSharedMemorySize, SMEM_ENC);
  cudaFuncSetAttribute(k_dec_step,    cudaFuncAttributeMaxDynamicSharedMemorySize, SMEM_DEC);

  k_embed<<<1024,256>>>(src,trg,user,prod,embW,userW,prodW);

  {
    dim3 g(G3/64, (SS*BB)/64);
    gemm_atb<64,64,32,4,4><<<g,256>>>(pX, WihF, bihF, pGiF, SS*BB, G3, EE);
    gemm_atb<64,64,32,4,4><<<g,256>>>(pX, WihB, bihB, pGiB, SS*BB, G3, EE);
  }

  k_enc_persist<<<ENC_BLOCKS,256,SMEM_ENC>>>(WhhF,bhhF,WhhB,bhhB);

  k_postenc<<<2048,256>>>();

  {
    dim3 g(HH/64, (SS*BB)/64);
    gemm_atb<64,64,32,4,4><<<g,256>>>(pEH, keyW, nullptr, pPK, SS*BB, HH, 2*HH);
  }

  k_hidden<<<dim3(HH/8,BB),256>>>(initW, initB);

  for (int t=0;t<LL;t++){
    int par=t&1;
    k_dec_step<<<128,128,SMEM_DEC>>>(t,par,dWih,dWhh,dbih,dbhh);
    k_qw<<<dim3(HH/8,BB),256>>>(queryW, par^1);
    k_scores<<<dim3(SS/8,BB),256>>>(energW, mask);
    k_softmax_s<<<BB,256>>>();
    k_context<<<dim3(2*HH/256,BB),256>>>();
    k_ch<<<dim3(HH/8,BB),256>>>(chW, par^1);
    k_gp<<<BB,256>>>(genpW, genpb, par^1, t);
    gemm_atb<32,128,32,4,4><<<dim3((VV+127)/128,1),256>>>(pCh, genW, nullptr, pLog, BB, VV, HH);
    k_vocab_out<<<BB,1024>>>(out, t);
    k_scatter<<<(BB*SS+255)/256,256>>>(out, src, t);
  }
}